// round 1
// baseline (speedup 1.0000x reference)
#include <cuda_runtime.h>

// Batched EKF step: predict(F = I + dt*shift, Q) then 3-obs update.
// Inputs (metadata order): x [B,6,1], P [B,6,6], delta_t [B], Q [B,6,6],
//                          z [B,3,1], R [B,3,3]   (all float32)
// Output: concat(flatten(x_upd [B,6,1]), flatten(P_upd [B,6,6])) = 42*B floats.

__global__ __launch_bounds__(256)
void ekf_step_kernel(const float* __restrict__ x_in,
                     const float* __restrict__ P_in,
                     const float* __restrict__ dt_in,
                     const float* __restrict__ Q_in,
                     const float* __restrict__ z_in,
                     const float* __restrict__ R_in,
                     float* __restrict__ out,
                     int B)
{
    int b = blockIdx.x * blockDim.x + threadIdx.x;
    if (b >= B) return;

    const float dt = dt_in[b];

    // ---- loads (vectorized where alignment allows) ----
    float x[6];
    {
        const float2* xp = reinterpret_cast<const float2*>(x_in + (size_t)b * 6);
        float2 a0 = xp[0], a1 = xp[1], a2 = xp[2];
        x[0] = a0.x; x[1] = a0.y; x[2] = a1.x;
        x[3] = a1.y; x[4] = a2.x; x[5] = a2.y;
    }

    float P[36];   // raw P, later reused as P_upd
    float Pp[36];  // starts as Q, becomes P_pred
    {
        const float4* pp = reinterpret_cast<const float4*>(P_in + (size_t)b * 36);
        const float4* qp = reinterpret_cast<const float4*>(Q_in + (size_t)b * 36);
        #pragma unroll
        for (int i = 0; i < 9; i++) {
            float4 v = pp[i];
            P[4*i+0] = v.x; P[4*i+1] = v.y; P[4*i+2] = v.z; P[4*i+3] = v.w;
        }
        #pragma unroll
        for (int i = 0; i < 9; i++) {
            float4 v = qp[i];
            Pp[4*i+0] = v.x; Pp[4*i+1] = v.y; Pp[4*i+2] = v.z; Pp[4*i+3] = v.w;
        }
    }

    float z[3];
    {
        const float* zp = z_in + (size_t)b * 3;
        z[0] = zp[0]; z[1] = zp[1]; z[2] = zp[2];
    }
    float R[9];
    {
        const float* rp = R_in + (size_t)b * 9;
        #pragma unroll
        for (int i = 0; i < 9; i++) R[i] = rp[i];
    }

    // ---- predict ----
    float xp[6];
    #pragma unroll
    for (int i = 0; i < 3; i++) xp[i] = fmaf(dt, x[i + 3], x[i]);
    #pragma unroll
    for (int i = 3; i < 6; i++) xp[i] = x[i];

    const float dt2 = dt * dt;
    // P_pred = F P F^T + Q, with F = I + dt*E (E: (0,3),(1,4),(2,5))
    #pragma unroll
    for (int i = 0; i < 6; i++) {
        #pragma unroll
        for (int j = 0; j < 6; j++) {
            float v = P[i*6 + j];
            if (i < 3)          v = fmaf(dt,  P[(i+3)*6 + j],     v);
            if (j < 3)          v = fmaf(dt,  P[i*6 + (j+3)],     v);
            if (i < 3 && j < 3) v = fmaf(dt2, P[(i+3)*6 + (j+3)], v);
            Pp[i*6 + j] += v;
        }
    }

    // ---- update ----
    // S = Pp[:3,:3] + R, invert via adjugate
    float s00 = Pp[0]  + R[0], s01 = Pp[1]  + R[1], s02 = Pp[2]  + R[2];
    float s10 = Pp[6]  + R[3], s11 = Pp[7]  + R[4], s12 = Pp[8]  + R[5];
    float s20 = Pp[12] + R[6], s21 = Pp[13] + R[7], s22 = Pp[14] + R[8];

    float c00 = s11*s22 - s12*s21;
    float c01 = s02*s21 - s01*s22;
    float c02 = s01*s12 - s02*s11;
    float c10 = s12*s20 - s10*s22;
    float c11 = s00*s22 - s02*s20;
    float c12 = s02*s10 - s00*s12;
    float c20 = s10*s21 - s11*s20;
    float c21 = s01*s20 - s00*s21;
    float c22 = s00*s11 - s01*s10;

    float det = s00*c00 + s01*c10 + s02*c20;
    float inv_det = 1.0f / det;

    float Si[9] = { c00*inv_det, c01*inv_det, c02*inv_det,
                    c10*inv_det, c11*inv_det, c12*inv_det,
                    c20*inv_det, c21*inv_det, c22*inv_det };

    // K = Pp[:, :3] @ Si   (6x3)
    float K[18];
    #pragma unroll
    for (int i = 0; i < 6; i++) {
        float p0 = Pp[i*6 + 0], p1 = Pp[i*6 + 1], p2 = Pp[i*6 + 2];
        #pragma unroll
        for (int j = 0; j < 3; j++) {
            K[i*3 + j] = p0 * Si[0*3 + j] + p1 * Si[1*3 + j] + p2 * Si[2*3 + j];
        }
    }

    float in0 = z[0] - xp[0];
    float in1 = z[1] - xp[1];
    float in2 = z[2] - xp[2];

    float xu[6];
    #pragma unroll
    for (int i = 0; i < 6; i++) {
        xu[i] = xp[i] + K[i*3+0]*in0 + K[i*3+1]*in1 + K[i*3+2]*in2;
    }

    // P_upd = Pp - K @ Pp[:3, :]   (reuse P[] as output buffer)
    #pragma unroll
    for (int i = 0; i < 6; i++) {
        float k0 = K[i*3+0], k1 = K[i*3+1], k2 = K[i*3+2];
        #pragma unroll
        for (int j = 0; j < 6; j++) {
            P[i*6 + j] = Pp[i*6 + j]
                       - (k0 * Pp[0*6 + j] + k1 * Pp[1*6 + j] + k2 * Pp[2*6 + j]);
        }
    }

    // ---- stores ----
    {
        float2* xo = reinterpret_cast<float2*>(out + (size_t)b * 6);
        xo[0] = make_float2(xu[0], xu[1]);
        xo[1] = make_float2(xu[2], xu[3]);
        xo[2] = make_float2(xu[4], xu[5]);
    }
    {
        float4* po = reinterpret_cast<float4*>(out + (size_t)B * 6 + (size_t)b * 36);
        #pragma unroll
        for (int i = 0; i < 9; i++) {
            po[i] = make_float4(P[4*i+0], P[4*i+1], P[4*i+2], P[4*i+3]);
        }
    }
}

extern "C" void kernel_launch(void* const* d_in, const int* in_sizes, int n_in,
                              void* d_out, int out_size)
{
    const float* x  = (const float*)d_in[0];
    const float* P  = (const float*)d_in[1];
    const float* dt = (const float*)d_in[2];
    const float* Q  = (const float*)d_in[3];
    const float* z  = (const float*)d_in[4];
    const float* R  = (const float*)d_in[5];
    float* out = (float*)d_out;

    int B = in_sizes[2];  // delta_t has B elements
    int threads = 256;
    int blocks = (B + threads - 1) / threads;
    ekf_step_kernel<<<blocks, threads>>>(x, P, dt, Q, z, R, out, B);
}